// round 15
// baseline (speedup 1.0000x reference)
#include <cuda_runtime.h>

#define NN 100000
#define NE 1000000
#define NBS ((NN + 255) / 256)  // 391 scan blocks

// ---- scratch (static device globals: allocation-free) ----
__device__ int g_is64;           // 1 if edge_index is int64, 0 if int32
__device__ int g_cnt[NN];
__device__ int g_tmp[NN];
__device__ int g_row[NN + 1];
__device__ int g_cur[NN];
__device__ int g_col[NE];
__device__ int g_bsums[NBS];
__device__ int g_boff[NBS + 1];
__device__ __align__(16) float g_agg[NN * 64];
__device__ __align__(16) float g_h[NN * 64];
__device__ __align__(16) float g_h2[NN * 64];

// ---- edge_index dtype detection ----
// int64 values < 2^32 (node ids are 0..NN-1, nonnegative): every odd 32-bit
// word is zero. Real int32 data has random ids at odd indices; P(all zero)~0.
__global__ void k_detect(const int* __restrict__ raw) {
    if (threadIdx.x == 0 && blockIdx.x == 0) {
        int is64 = 1;
        for (int i = 1; i < 64; i += 2)
            if (raw[i] != 0) { is64 = 0; break; }
        g_is64 = is64;
    }
}

__device__ __forceinline__ void load_edge(const int* __restrict__ raw, int e,
                                          int& src, int& dst) {
    if (g_is64) {
        const long long* e64 = (const long long*)raw;
        src = (int)e64[e];
        dst = (int)e64[NE + e];
    } else {
        src = raw[e];
        dst = raw[NE + e];
    }
}

// ---- CSR build ----
__global__ void k_zero_cnt() {
    int i = blockIdx.x * blockDim.x + threadIdx.x;
    if (i < NN) g_cnt[i] = 0;
}

__global__ void k_count(const int* __restrict__ raw) {
    int e = blockIdx.x * blockDim.x + threadIdx.x;
    if (e < NE) {
        int src, dst;
        load_edge(raw, e, src, dst);
        if ((unsigned)dst < NN) atomicAdd(&g_cnt[dst], 1);
    }
}

__global__ void k_scanA() {
    __shared__ int s[256];
    int tid = threadIdx.x;
    int i = blockIdx.x * 256 + tid;
    int v = (i < NN) ? g_cnt[i] : 0;
    s[tid] = v;
    __syncthreads();
    for (int off = 1; off < 256; off <<= 1) {
        int t = (tid >= off) ? s[tid - off] : 0;
        __syncthreads();
        s[tid] += t;
        __syncthreads();
    }
    if (i < NN) g_tmp[i] = s[tid];
    if (tid == 255) g_bsums[blockIdx.x] = s[255];
}

__global__ void k_scanB() {
    __shared__ int s[512];
    int tid = threadIdx.x;
    int v = (tid < NBS) ? g_bsums[tid] : 0;
    s[tid] = v;
    __syncthreads();
    for (int off = 1; off < 512; off <<= 1) {
        int t = (tid >= off) ? s[tid - off] : 0;
        __syncthreads();
        s[tid] += t;
        __syncthreads();
    }
    if (tid < NBS) g_boff[tid] = s[tid] - v;      // exclusive
    if (tid == NBS - 1) g_boff[NBS] = s[tid];     // total
}

__global__ void k_scanC() {
    int i = blockIdx.x * 256 + threadIdx.x;
    if (i < NN) {
        int ex = g_tmp[i] - g_cnt[i] + g_boff[blockIdx.x];
        g_row[i] = ex;
        g_cur[i] = ex;
    }
    if (i == 0) g_row[NN] = g_boff[NBS];
}

__global__ void k_fill(const int* __restrict__ raw) {
    int e = blockIdx.x * blockDim.x + threadIdx.x;
    if (e < NE) {
        int src, dst;
        load_edge(raw, e, src, dst);
        if ((unsigned)dst < NN && (unsigned)src < NN) {
            int idx = atomicAdd(&g_cur[dst], 1);
            if ((unsigned)idx < NE) g_col[idx] = src;
        }
    }
}

// ---- aggregation: 16 lanes per node, gather neighbor rows (no atomics) ----
// LAYER 1 reads harness input x (param); LAYER 2 reads g_h. Both write g_agg.
template <int LAYER>
__global__ void k_gather(const float* __restrict__ xparam) {
    int gid = blockIdx.x * blockDim.x + threadIdx.x;
    int node = gid >> 4;
    int lane = gid & 15;
    if (node >= NN) return;
    const float* src_base = (LAYER == 1) ? xparam : (const float*)g_h;
    int s = g_row[node];
    int e = g_row[node + 1];
    float4 acc = make_float4(0.f, 0.f, 0.f, 0.f);
    const float4* xv = (const float4*)src_base;
    for (int j = s; j < e; j++) {
        int src = g_col[j];
        float4 v = __ldg(&xv[src * 16 + lane]);
        acc.x += v.x; acc.y += v.y; acc.z += v.z; acc.w += v.w;
    }
    ((float4*)g_agg)[node * 16 + lane] = acc;
}

// ---- fused SAGE layer: out = relu(mean @ Wl.T + x @ Wr.T + b) ----
// LAYER 1: src = xparam, dst = g_h.  LAYER 2: src = g_h, dst = g_h2.
template <int LAYER>
__global__ void __launch_bounds__(256) k_dense(
        const float* __restrict__ xparam,
        const float* __restrict__ Wl, const float* __restrict__ Wr,
        const float* __restrict__ b) {
    __shared__ float sWl[64 * 64];   // transposed: [k][j]
    __shared__ float sWr[64 * 64];
    __shared__ float sb[64];
    int tid = threadIdx.x;
    for (int idx = tid; idx < 4096; idx += 256) {
        int k = idx >> 6, j = idx & 63;
        sWl[idx] = Wl[j * 64 + k];
        sWr[idx] = Wr[j * 64 + k];
    }
    if (tid < 64) sb[tid] = b[tid];
    __syncthreads();

    int node = blockIdx.x * 256 + tid;
    if (node >= NN) return;

    const float* src = (LAYER == 1) ? xparam : (const float*)g_h;
    float* dst = (LAYER == 1) ? (float*)g_h : (float*)g_h2;

    int deg = g_row[node + 1] - g_row[node];
    float inv = 1.0f / (float)(deg > 1 ? deg : 1);

    float4 acc[16];
    const float4* sb4 = (const float4*)sb;
#pragma unroll
    for (int j4 = 0; j4 < 16; j4++) acc[j4] = sb4[j4];

    const float4* xr = (const float4*)(src + (size_t)node * 64);
    const float4* ar = (const float4*)((const float*)g_agg + (size_t)node * 64);
    const float4* wl4 = (const float4*)sWl;
    const float4* wr4 = (const float4*)sWr;

#pragma unroll 1
    for (int k4 = 0; k4 < 16; k4++) {
        float4 xv = xr[k4];
        float4 av = ar[k4];
        float xs[4] = {xv.x, xv.y, xv.z, xv.w};
        float ms[4] = {av.x * inv, av.y * inv, av.z * inv, av.w * inv};
#pragma unroll
        for (int kk = 0; kk < 4; kk++) {
            int k = k4 * 4 + kk;
#pragma unroll
            for (int j4 = 0; j4 < 16; j4++) {
                float4 wl = wl4[k * 16 + j4];
                float4 wr = wr4[k * 16 + j4];
                acc[j4].x += xs[kk] * wr.x + ms[kk] * wl.x;
                acc[j4].y += xs[kk] * wr.y + ms[kk] * wl.y;
                acc[j4].z += xs[kk] * wr.z + ms[kk] * wl.z;
                acc[j4].w += xs[kk] * wr.w + ms[kk] * wl.w;
            }
        }
    }

    float4* o = (float4*)(dst + (size_t)node * 64);
#pragma unroll
    for (int j4 = 0; j4 < 16; j4++) {
        float4 a = acc[j4];
        a.x = fmaxf(a.x, 0.f);
        a.y = fmaxf(a.y, 0.f);
        a.z = fmaxf(a.z, 0.f);
        a.w = fmaxf(a.w, 0.f);
        o[j4] = a;
    }
}

// ---- output head: out = g_h2 @ W_out.T + b_out  (10 classes) ----
__global__ void __launch_bounds__(256) k_out(
        const float* __restrict__ Wo, const float* __restrict__ bo,
        float* __restrict__ out) {
    __shared__ float sW[640];
    __shared__ float sbo[10];
    int tid = threadIdx.x;
    for (int i = tid; i < 640; i += 256) sW[i] = Wo[i];
    if (tid < 10) sbo[tid] = bo[tid];
    __syncthreads();

    int node = blockIdx.x * 256 + tid;
    if (node >= NN) return;

    float4 xr[16];
    const float4* hp = (const float4*)((const float*)g_h2 + (size_t)node * 64);
#pragma unroll
    for (int i = 0; i < 16; i++) xr[i] = hp[i];

    const float4* w4 = (const float4*)sW;
#pragma unroll
    for (int c = 0; c < 10; c++) {
        float acc = sbo[c];
#pragma unroll
        for (int k4 = 0; k4 < 16; k4++) {
            float4 w = w4[c * 16 + k4];
            acc += xr[k4].x * w.x + xr[k4].y * w.y + xr[k4].z * w.z + xr[k4].w * w.w;
        }
        out[(size_t)node * 10 + c] = acc;
    }
}

extern "C" void kernel_launch(void* const* d_in, const int* in_sizes, int n_in,
                              void* d_out, int out_size) {
    const float* x       = (const float*)d_in[0];
    const int* ei_raw    = (const int*)d_in[1];   // int32 OR int64 (detected on device)
    const float* W1l     = (const float*)d_in[2];
    const float* W1r     = (const float*)d_in[3];
    const float* b1      = (const float*)d_in[4];
    const float* W2l     = (const float*)d_in[5];
    const float* W2r     = (const float*)d_in[6];
    const float* b2      = (const float*)d_in[7];
    const float* Wo      = (const float*)d_in[8];
    const float* bo      = (const float*)d_in[9];
    float* out           = (float*)d_out;

    // Detect edge_index dtype, then build CSR (once, reused by both layers)
    k_detect<<<1, 32>>>(ei_raw);
    k_zero_cnt<<<(NN + 255) / 256, 256>>>();
    k_count<<<(NE + 255) / 256, 256>>>(ei_raw);
    k_scanA<<<NBS, 256>>>();
    k_scanB<<<1, 512>>>();
    k_scanC<<<NBS, 256>>>();
    k_fill<<<(NE + 255) / 256, 256>>>(ei_raw);

    // Layer 1
    k_gather<1><<<(NN * 16 + 255) / 256, 256>>>(x);
    k_dense<1><<<(NN + 255) / 256, 256>>>(x, W1l, W1r, b1);
    // Layer 2
    k_gather<2><<<(NN * 16 + 255) / 256, 256>>>(x);
    k_dense<2><<<(NN + 255) / 256, 256>>>(x, W2l, W2r, b2);
    // Head
    k_out<<<(NN + 255) / 256, 256>>>(Wo, bo, out);
}